// round 14
// baseline (speedup 1.0000x reference)
#include <cuda_runtime.h>

// Shapes: probs (2,2,32,512,512) fp32, gt_mask (2,32,512,512) int32.
// Output: scalar fp32 = mean over all of (probs - onehot(target))^2,
// target = (gt == 1) since ignore_index=2 -> 0 and clamp [0,1].
//
// Contiguous per-CTA chunking: 1024 CTAs x 4096 contiguous vec-groups.
// Each CTA walks linearly through a 64KB region per stream (vs 4.85MB
// grid-stride jumps) to maximize DRAM row-buffer hits; binder is HBM
// (~79% of spec at NAT clock, LTS path not saturated at ~3500 B/cyc).
// b (batch) is constant per chunk -> hoisted. Tail: one packed 64-bit
// atomicAdd per block {count[52:], fixed-point sum x 2^20 [0:52)} ->
// bitwise-deterministic graph replays.

constexpr int DHW      = 32 * 512 * 512;   // 8388608 = 2^23
constexpr int NGT      = 2 * DHW;          // 16777216
constexpr int VEC      = NGT / 4;          // 4194304 int4/float4 groups
constexpr int DHW4     = DHW / 4;          // 2097152 = 2^21
constexpr int BLOCKS   = 1024;
constexpr int THREADS  = 256;
constexpr int CHUNK    = VEC / BLOCKS;     // 4096 contiguous groups per CTA
constexpr int TRIPS    = CHUNK / THREADS;  // 16
static_assert(CHUNK * BLOCKS == VEC, "exact tiling");
static_assert(TRIPS * THREADS == CHUNK, "exact tiling");
static_assert((DHW4 % CHUNK) == 0, "chunk never straddles a batch boundary");

constexpr unsigned long long COUNT_ONE = 1ULL << 52;
constexpr unsigned long long SUM_MASK  = COUNT_ONE - 1ULL;

__device__ unsigned long long g_accum;  // zero-init at load; reset by last block

__device__ __forceinline__ float warp_sum(float v) {
    #pragma unroll
    for (int o = 16; o > 0; o >>= 1)
        v += __shfl_xor_sync(0xFFFFFFFFu, v, o);
    return v;
}

__global__ __launch_bounds__(THREADS) void mse_chunk_kernel(
    const float* __restrict__ probs, const int* __restrict__ gt,
    float* __restrict__ out)
{
    const int base = blockIdx.x * CHUNK;         // chunk start (vec groups)
    const int b    = base >> 21;                 // batch: constant per chunk
    const int r0   = base & (DHW4 - 1);          // spatial offset of chunk

    // Stream base pointers for this chunk (all contiguous 64KB walks).
    const int4*   __restrict__ gp  = reinterpret_cast<const int4*>(gt) + base;
    const float4* __restrict__ p0p = reinterpret_cast<const float4*>(probs)
                                   + (size_t)(2 * b    ) * DHW4 + r0;   // c = 0
    const float4* __restrict__ p1p = reinterpret_cast<const float4*>(probs)
                                   + (size_t)(2 * b + 1) * DHW4 + r0;   // c = 1

    float acc = 0.0f;
    int off = threadIdx.x;
    #pragma unroll 1
    for (int t = 0; t < TRIPS; t++, off += THREADS) {
        int4   g  = __ldcs(gp  + off);
        float4 p0 = __ldcs(p0p + off);
        float4 p1 = __ldcs(p1p + off);

        // onehot: oh0 = (gt != 1), oh1 = (gt == 1)
        float d;
        d = p0.x - (float)(g.x != 1); acc = fmaf(d, d, acc);
        d = p1.x - (float)(g.x == 1); acc = fmaf(d, d, acc);
        d = p0.y - (float)(g.y != 1); acc = fmaf(d, d, acc);
        d = p1.y - (float)(g.y == 1); acc = fmaf(d, d, acc);
        d = p0.z - (float)(g.z != 1); acc = fmaf(d, d, acc);
        d = p1.z - (float)(g.z == 1); acc = fmaf(d, d, acc);
        d = p0.w - (float)(g.w != 1); acc = fmaf(d, d, acc);
        d = p1.w - (float)(g.w == 1); acc = fmaf(d, d, acc);
    }

    // Block reduction: warp shuffles -> smem -> thread 0
    __shared__ float smem[THREADS / 32];
    acc = warp_sum(acc);
    int lane = threadIdx.x & 31;
    int wid  = threadIdx.x >> 5;
    if (lane == 0) smem[wid] = acc;
    __syncthreads();

    if (threadIdx.x == 0) {
        float v = 0.0f;
        #pragma unroll
        for (int i = 0; i < THREADS / 32; i++) v += smem[i];

        // Fixed-point encode (round to nearest) + arrival count, one atom.
        unsigned long long mine =
            COUNT_ONE | (unsigned long long)(v * 1048576.0f + 0.5f);
        unsigned long long prev = atomicAdd(&g_accum, mine);
        unsigned long long now  = prev + mine;

        if ((now >> 52) == (unsigned long long)gridDim.x) {
            float total = (float)((double)(now & SUM_MASK) * 0x1p-45);
            out[0] = total;                 // 2^-20 (scale) * 2^-25 (1/N)
            g_accum = 0ULL;                 // restore invariant for next replay
        }
    }
}

extern "C" void kernel_launch(void* const* d_in, const int* in_sizes, int n_in,
                              void* d_out, int out_size)
{
    const float* probs = (const float*)d_in[0];
    const int*   gt    = (const int*)d_in[1];
    float*       out   = (float*)d_out;

    mse_chunk_kernel<<<BLOCKS, THREADS>>>(probs, gt, out);
}

// round 15
// speedup vs baseline: 1.1299x; 1.1299x over previous
#include <cuda_runtime.h>

// Shapes: probs (2,2,32,512,512) fp32, gt_mask (2,32,512,512) int32.
// Output: scalar fp32 = mean over all of (probs - onehot(target))^2,
// target = (gt == 1) since ignore_index=2 -> 0 and clamp [0,1].
//
// FINAL (R13 config, measured best 33.57/33.79us across two runs):
// plain streaming-load grid-stride loop, full-residency grid
// (1184 = 148 SMs x 8 CTAs x 256 thr). 14-round search measured every
// lever in both directions: register unrolling x2/x4 (R5/R8: regress),
// cp.async pipeline depth 3/4 (R9/R10: tie/regress), contiguous per-CTA
// chunking (R14: regress -6% DRAM). All structures plateau at
// 6.0-6.33 TB/s = 76-79% of HBM spec — the practical mixed-read
// ceiling; this config reaches it with the least overhead (26 regs,
// no staging).
// Tail: one packed 64-bit atomicAdd per block {count[52:], fixed-point
// sum x 2^20 [0:52)}; integer adds -> bitwise-deterministic replays.

constexpr int DHW      = 32 * 512 * 512;   // 8388608 = 2^23
constexpr int NGT      = 2 * DHW;          // 16777216
constexpr int VEC      = NGT / 4;          // 4194304 int4/float4 groups
constexpr int DHW4     = DHW / 4;          // 2097152 = 2^21
constexpr int BLOCKS   = 1184;             // 148 SMs * 8 CTAs
constexpr int THREADS  = 256;

// Fixed-point: block partial < 2^15 -> *2^20 < 2^35; 1184 blocks -> < 2^46.
// Count lives in bits [52:]; no overlap with the sum field.
constexpr unsigned long long COUNT_ONE = 1ULL << 52;
constexpr unsigned long long SUM_MASK  = COUNT_ONE - 1ULL;

__device__ unsigned long long g_accum;  // zero-init at load; reset by last block

__device__ __forceinline__ float warp_sum(float v) {
    #pragma unroll
    for (int o = 16; o > 0; o >>= 1)
        v += __shfl_xor_sync(0xFFFFFFFFu, v, o);
    return v;
}

__global__ __launch_bounds__(THREADS) void mse_fused_kernel(
    const float* __restrict__ probs, const int* __restrict__ gt,
    float* __restrict__ out)
{
    const float4* __restrict__ p4 = reinterpret_cast<const float4*>(probs);
    const int4*   __restrict__ g4 = reinterpret_cast<const int4*>(gt);

    float acc = 0.0f;
    const int stride = gridDim.x * blockDim.x;
    for (int idx = blockIdx.x * blockDim.x + threadIdx.x; idx < VEC; idx += stride) {
        int4 g = __ldcs(&g4[idx]);
        int b = idx >> 21;            // DHW4 = 2^21
        int r = idx & (DHW4 - 1);
        // probs layout (B, C, D, H, W): channel stride = DHW
        float4 p0 = __ldcs(&p4[(size_t)(2 * b    ) * DHW4 + r]);  // c = 0
        float4 p1 = __ldcs(&p4[(size_t)(2 * b + 1) * DHW4 + r]);  // c = 1

        // onehot: oh0 = (gt != 1), oh1 = (gt == 1)
        float d;
        d = p0.x - (float)(g.x != 1); acc = fmaf(d, d, acc);
        d = p1.x - (float)(g.x == 1); acc = fmaf(d, d, acc);
        d = p0.y - (float)(g.y != 1); acc = fmaf(d, d, acc);
        d = p1.y - (float)(g.y == 1); acc = fmaf(d, d, acc);
        d = p0.z - (float)(g.z != 1); acc = fmaf(d, d, acc);
        d = p1.z - (float)(g.z == 1); acc = fmaf(d, d, acc);
        d = p0.w - (float)(g.w != 1); acc = fmaf(d, d, acc);
        d = p1.w - (float)(g.w == 1); acc = fmaf(d, d, acc);
    }

    // Block reduction: warp shuffles -> smem -> thread 0
    __shared__ float smem[THREADS / 32];
    acc = warp_sum(acc);
    int lane = threadIdx.x & 31;
    int wid  = threadIdx.x >> 5;
    if (lane == 0) smem[wid] = acc;
    __syncthreads();

    if (threadIdx.x == 0) {
        float v = 0.0f;
        #pragma unroll
        for (int i = 0; i < THREADS / 32; i++) v += smem[i];

        // Fixed-point encode (round to nearest) + arrival count, one atom.
        unsigned long long mine =
            COUNT_ONE | (unsigned long long)(v * 1048576.0f + 0.5f);
        unsigned long long prev = atomicAdd(&g_accum, mine);
        unsigned long long now  = prev + mine;

        if ((now >> 52) == (unsigned long long)gridDim.x) {
            // Last block: low bits hold the exact fixed-point total.
            float total = (float)((double)(now & SUM_MASK) * 0x1p-45);
            out[0] = total;                 // 2^-20 (scale) * 2^-25 (1/N)
            g_accum = 0ULL;                 // restore invariant for next replay
        }
    }
}

extern "C" void kernel_launch(void* const* d_in, const int* in_sizes, int n_in,
                              void* d_out, int out_size)
{
    const float* probs = (const float*)d_in[0];
    const int*   gt    = (const int*)d_in[1];
    float*       out   = (float*)d_out;

    mse_fused_kernel<<<BLOCKS, THREADS>>>(probs, gt, out);
}